// round 16
// baseline (speedup 1.0000x reference)
#include <cuda_runtime.h>
#include <cuda_fp16.h>
#include <cstdint>
#include <cstddef>

// Problem constants
#define NUQ 100000
#define NIQ 100000
#define DD 128
#define NSS 5
#define EE 500000
#define NSEG (NSS * NUQ)          // 500000 segments per side
#define NEDGE (NSS * EE)          // 2500000 edges per side
#define KTOT (NSS * DD)           // 640
#define TSEG (2 * NSEG)           // 1000000 total segments
#define TEDGE (2 * NEDGE)         // 5000000 total edges
#define GM (2 * NUQ)              // 200000 output rows (user block then item block)

// ---------------- static scratch (device globals; no allocation) -----------
__device__ __half g_Wch[KTOT * DD];                  // cumulative weights [640 k][128 n] fp16
__device__ __half g_uh[(size_t)NUQ * DD];            // fp16 copy of user_inputs
__device__ __half g_ih[(size_t)NIQ * DD];            // fp16 copy of item_inputs
__device__ int    g_cnt[TSEG];                       // per-segment edge counts
__device__ int    g_rp[TSEG + 1];                    // CSR row pointers
__device__ int    g_cur[TSEG];                       // scatter cursors
__device__ int2   g_edge[TEDGE];                     // CSR packed (col, val-bits)
__device__ int    g_bsum[1024];                      // scan block sums

// ---------------- cumulative weight stack -----------------------------------
// weight layout: (DIN, DOUT, NS) row-major -> idx = din*DOUT*NS + dout*NS + s
__global__ void k_wc(const float* __restrict__ w) {
    int din = blockIdx.x;     // 128 (k within support)
    int dout = threadIdx.x;   // 128 (n)
    float acc = 0.f;
#pragma unroll
    for (int s = 0; s < NSS; s++) {
        acc += w[din * (DD * NSS) + dout * NSS + s];
        g_Wch[(size_t)(s * DD + din) * DD + dout] = __float2half(acc);
    }
}

// ---------------- fp16 copies of dense inputs --------------------------------
__global__ void k_tohalf(const float4* __restrict__ uin, const float4* __restrict__ iin) {
    const int n4 = NUQ * DD / 4;   // 3.2M float4 per side
    for (int i = blockIdx.x * blockDim.x + threadIdx.x; i < 2 * n4;
         i += gridDim.x * blockDim.x) {
        int side = (i >= n4);
        int j = i - side * n4;
        float4 v = side ? iin[j] : uin[j];
        __half2 a = __floats2half2_rn(v.x, v.y);
        __half2 b = __floats2half2_rn(v.z, v.w);
        uint2 st;
        st.x = *(const unsigned*)&a;
        st.y = *(const unsigned*)&b;
        ((uint2*)(side ? g_ih : g_uh))[j] = st;
    }
}

// ---------------- CSR build (best-measured R7 configuration) -----------------
__global__ void k_zero_counts() {
    for (int i = blockIdx.x * blockDim.x + threadIdx.x; i < TSEG;
         i += gridDim.x * blockDim.x)
        g_cnt[i] = 0;
}

__global__ void k_hist(const int* __restrict__ urows, const int* __restrict__ irows) {
    for (int i = blockIdx.x * blockDim.x + threadIdx.x; i < TEDGE;
         i += gridDim.x * blockDim.x) {
        int side = (i >= NEDGE);
        int e = i - side * NEDGE;
        const int* rows = side ? irows : urows;
        int s = e / EE;
        int r = rows[e];
        atomicAdd(&g_cnt[side * NSEG + s * NUQ + r], 1);
    }
}

__global__ void k_scan1() {
    __shared__ int sh[1024];
    int tid = threadIdx.x;
    int i = blockIdx.x * 1024 + tid;
    int v = (i < TSEG) ? g_cnt[i] : 0;
    sh[tid] = v;
    __syncthreads();
    for (int off = 1; off < 1024; off <<= 1) {
        int t = (tid >= off) ? sh[tid - off] : 0;
        __syncthreads();
        sh[tid] += t;
        __syncthreads();
    }
    if (i < TSEG) g_rp[i] = sh[tid] - v;   // local exclusive
    if (tid == 1023) g_bsum[blockIdx.x] = sh[1023];
}

__global__ void k_scan2(int nb) {
    __shared__ int sh[1024];
    int tid = threadIdx.x;
    int v = (tid < nb) ? g_bsum[tid] : 0;
    sh[tid] = v;
    __syncthreads();
    for (int off = 1; off < 1024; off <<= 1) {
        int t = (tid >= off) ? sh[tid - off] : 0;
        __syncthreads();
        sh[tid] += t;
        __syncthreads();
    }
    if (tid < nb) g_bsum[tid] = sh[tid] - v;  // exclusive block offsets
}

__global__ void k_scan3() {
    int i = blockIdx.x * 1024 + threadIdx.x;
    if (i < TSEG) {
        int v = g_rp[i] + g_bsum[blockIdx.x];
        g_rp[i] = v;
        g_cur[i] = v;
    }
    if (i == 0) g_rp[TSEG] = TEDGE;
}

__global__ void k_scatter(const int* __restrict__ urows, const int* __restrict__ ucols,
                          const float* __restrict__ uvals,
                          const int* __restrict__ irows, const int* __restrict__ icols,
                          const float* __restrict__ ivals) {
    for (int i = blockIdx.x * blockDim.x + threadIdx.x; i < TEDGE;
         i += gridDim.x * blockDim.x) {
        int side = (i >= NEDGE);
        int e = i - side * NEDGE;
        const int* rows = side ? irows : urows;
        const int* cols = side ? icols : ucols;
        const float* vals = side ? ivals : uvals;
        int s = e / EE;
        int seg = side * NSEG + s * NUQ + rows[e];
        int p = atomicAdd(&g_cur[seg], 1);
        g_edge[p] = make_int2(cols[e], __float_as_int(vals[e]));
    }
}

// ---------------- FUSED SPMM + FP16 GEMM + ReLU ------------------------------
// One CTA per 128 output rows, 512 threads (16 warps), 1 CTA/SM.
// Phase 1: warps gather/accumulate the CTA's 640 (row,support) segments into a
//          resident smem A-tile [128][640] fp16 (stride 648 halves).
// Phase 2: mma.sync GEMM: A from resident smem (ldmatrix), B streamed via
//          double-buffered cp.async. Fused ReLU epilogue to out.
#define BM 128
#define BK 32
#define ASTR 648   // A smem stride in halves (1296B rows: 4-bank offset, LDSM-clean)
#define BSH 136    // B smem stride in halves (272B rows -> conflict-free LDSM)
#define NK (KTOT / BK)   // 20
#define A_SM_BYTES (BM * ASTR * 2)                   // 165888
#define B_SM_BYTES (2 * BK * BSH * 2)                // 17408
#define FUSED_SMEM (A_SM_BYTES + B_SM_BYTES)         // 183296

#define CPA(dst, src) asm volatile("cp.async.cg.shared.global [%0], [%1], 16;\n" :: "r"(dst), "l"(src))
#define CPC()         asm volatile("cp.async.commit_group;\n")
#define CPW(n)        asm volatile("cp.async.wait_group %0;\n" :: "n"(n))

#define LDSM4(r, addr)                                                         \
    asm volatile("ldmatrix.sync.aligned.m8n8.x4.shared.b16 {%0,%1,%2,%3}, [%4];" \
                 : "=r"((r)[0]), "=r"((r)[1]), "=r"((r)[2]), "=r"((r)[3])      \
                 : "r"(addr))
#define LDSM4T(r, addr)                                                        \
    asm volatile("ldmatrix.sync.aligned.m8n8.x4.trans.shared.b16 {%0,%1,%2,%3}, [%4];" \
                 : "=r"((r)[0]), "=r"((r)[1]), "=r"((r)[2]), "=r"((r)[3])      \
                 : "r"(addr))

#define MMA_F16(d, a, b0, b1)                                                  \
    asm volatile(                                                              \
        "mma.sync.aligned.m16n8k16.row.col.f32.f16.f16.f32 "                   \
        "{%0,%1,%2,%3}, {%4,%5,%6,%7}, {%8,%9}, {%0,%1,%2,%3};\n"              \
        : "+f"((d)[0]), "+f"((d)[1]), "+f"((d)[2]), "+f"((d)[3])               \
        : "r"((a)[0]), "r"((a)[1]), "r"((a)[2]), "r"((a)[3]),                  \
          "r"(b0), "r"(b1))

__global__ void __launch_bounds__(512, 1) k_fused(float* __restrict__ out) {
    extern __shared__ __half sm[];
    __half* Atile = sm;                          // [128][648]
    __half* Btile = sm + BM * ASTR;              // [2][32][136]
    uint32_t smbA = (uint32_t)__cvta_generic_to_shared(Atile);
    uint32_t smbB = (uint32_t)__cvta_generic_to_shared(Btile);

    int tid = threadIdx.x;
    int wid = tid >> 5, lane = tid & 31;
    int mbase = blockIdx.x * BM;

    // ================= Phase 1: gather segments into smem A ================
    // 640 segments = 128 tile-rows x 5 supports; warp w handles seg_i = w, w+16, ...
    for (int seg_i = wid; seg_i < BM * NSS; seg_i += 16) {
        int tr = seg_i & 127;         // tile row
        int s = seg_i >> 7;           // support
        int grow = mbase + tr;
        float4 acc = make_float4(0.f, 0.f, 0.f, 0.f);
        if (grow < GM) {
            int side = (grow >= NUQ);
            int r = grow - side * NUQ;
            const __half* dense = side ? g_uh : g_ih;
            int gseg = side * NSEG + s * NUQ + r;
            int b = g_rp[gseg];
            int en = g_rp[gseg + 1];
            for (int e = b; e < en; e++) {
                int2 ed = __ldg(&g_edge[e]);
                float v = __int_as_float(ed.y);
                uint2 xh = __ldg(((const uint2*)(dense + (size_t)ed.x * DD)) + lane);
                float2 x0 = __half22float2(*(const __half2*)&xh.x);
                float2 x1 = __half22float2(*(const __half2*)&xh.y);
                acc.x += v * x0.x;
                acc.y += v * x0.y;
                acc.z += v * x1.x;
                acc.w += v * x1.y;
            }
        }
        __half2 h0 = __floats2half2_rn(acc.x, acc.y);
        __half2 h1 = __floats2half2_rn(acc.z, acc.w);
        uint2 st;
        st.x = *(const unsigned*)&h0;
        st.y = *(const unsigned*)&h1;
        *(uint2*)(Atile + tr * ASTR + s * DD + lane * 4) = st;
    }
    __syncthreads();   // A fully built and visible

    // ================= Phase 2: GEMM from resident A =======================
    int warpm = wid & 3;       // 0..3  (32 rows each)
    int warpn = wid >> 2;      // 0..3  (32 cols each)
    int gid = lane >> 2;       // 0..7
    int tig = lane & 3;        // 0..3

    float c[2][4][4];
#pragma unroll
    for (int mi = 0; mi < 2; mi++)
#pragma unroll
        for (int ni = 0; ni < 4; ni++)
#pragma unroll
            for (int r = 0; r < 4; r++) c[mi][ni][r] = 0.f;

    // B cp.async chunk map: 512 chunks of 16B (32 k-rows x 16 chunks), one/thread
    int bk = tid >> 4, bc = tid & 15;
    const __half* bsrc = g_Wch + (size_t)bk * DD + bc * 8;
    uint32_t bdst[2];
#pragma unroll
    for (int bf = 0; bf < 2; bf++)
        bdst[bf] = smbB + (uint32_t)((bf * BK * BSH + bk * BSH + bc * 8) * 2);

    // ldmatrix per-lane addresses
    uint32_t aAddr[2];   // two 16-row tiles per warp
    uint32_t bAddr[2][2];
    {
        int arow_f = (lane & 15);
        int akk = (lane >> 4) * 8;                  // k offset within 16
#pragma unroll
        for (int mi = 0; mi < 2; mi++) {
            int row = warpm * 32 + mi * 16 + arow_f;
            aAddr[mi] = smbA + (uint32_t)((row * ASTR + akk) * 2);
        }
        int j = lane >> 3;                          // 0..3
        int brow_f = (j & 1) * 8 + (lane & 7);      // k within 16
        int bn_f = (j >> 1) * 8;                    // n offset within 16
#pragma unroll
        for (int bf = 0; bf < 2; bf++)
#pragma unroll
            for (int ni2 = 0; ni2 < 2; ni2++) {
                int nn = warpn * 32 + ni2 * 16 + bn_f;
                bAddr[bf][ni2] = smbB + (uint32_t)((bf * BK * BSH + brow_f * BSH + nn) * 2);
            }
    }

    // prologue: B stage 0 into buffer 0
    CPA(bdst[0], bsrc);
    CPC();

    for (int kt = 0; kt < NK; kt++) {
        int buf = kt & 1;
        if (kt + 1 < NK) {
            CPA(bdst[buf ^ 1], bsrc + (size_t)((kt + 1) * BK) * DD);
            CPC();
            CPW(1);
        } else {
            CPW(0);
        }
        __syncthreads();

#pragma unroll
        for (int ks = 0; ks < 2; ks++) {
            int kg = kt * BK + ks * 16;             // global k for A
            uint32_t a[2][4], b[2][4];
#pragma unroll
            for (int mi = 0; mi < 2; mi++)
                LDSM4(a[mi], aAddr[mi] + kg * 2);
#pragma unroll
            for (int ni2 = 0; ni2 < 2; ni2++)
                LDSM4T(b[ni2], bAddr[buf][ni2] + (ks * 16) * (BSH * 2));
#pragma unroll
            for (int mi = 0; mi < 2; mi++)
#pragma unroll
                for (int ni2 = 0; ni2 < 2; ni2++) {
                    MMA_F16(c[mi][ni2 * 2 + 0], a[mi], b[ni2][0], b[ni2][1]);
                    MMA_F16(c[mi][ni2 * 2 + 1], a[mi], b[ni2][2], b[ni2][3]);
                }
        }
        __syncthreads();
    }

    // epilogue: relu + store
#pragma unroll
    for (int mi = 0; mi < 2; mi++) {
        int row0 = mbase + warpm * 32 + mi * 16 + gid;
        int row1 = row0 + 8;
#pragma unroll
        for (int ni = 0; ni < 4; ni++) {
            int col = warpn * 32 + ni * 8 + tig * 2;
            if (row0 < GM) {
                float2 v;
                v.x = fmaxf(c[mi][ni][0], 0.f);
                v.y = fmaxf(c[mi][ni][1], 0.f);
                *(float2*)(out + (size_t)row0 * DD + col) = v;
            }
            if (row1 < GM) {
                float2 v;
                v.x = fmaxf(c[mi][ni][2], 0.f);
                v.y = fmaxf(c[mi][ni][3], 0.f);
                *(float2*)(out + (size_t)row1 * DD + col) = v;
            }
        }
    }
}

// ---------------- launcher --------------------------------------------------
extern "C" void kernel_launch(void* const* d_in, const int* in_sizes, int n_in,
                              void* d_out, int out_size) {
    const float* uin   = (const float*)d_in[0];   // user_inputs  [NU,128]
    const float* iin   = (const float*)d_in[1];   // item_inputs  [NI,128]
    const float* w     = (const float*)d_in[2];   // weight       [128,128,5]
    const int*   urows = (const int*)d_in[3];     // u_rows [5,E]
    const int*   ucols = (const int*)d_in[4];
    const float* uvals = (const float*)d_in[5];
    const int*   irows = (const int*)d_in[6];
    const int*   icols = (const int*)d_in[7];
    const float* ivals = (const float*)d_in[8];
    float* out = (float*)d_out;                   // [2*NU*128]: user then item

    (void)in_sizes; (void)n_in; (void)out_size;

    // 1. cumulative weight stack (fp16) + fp16 input copies
    k_wc<<<DD, DD>>>(w);
    k_tohalf<<<4096, 256>>>((const float4*)uin, (const float4*)iin);

    // 2. CSR build
    k_zero_counts<<<2048, 256>>>();
    k_hist<<<4096, 256>>>(urows, irows);
    int nblk = (TSEG + 1023) / 1024;   // 977
    k_scan1<<<nblk, 1024>>>();
    k_scan2<<<1, 1024>>>(nblk);
    k_scan3<<<nblk, 1024>>>();
    k_scatter<<<4096, 256>>>(urows, ucols, uvals, irows, icols, ivals);

    // 3. fused SPMM + GEMM + ReLU (no P round-trip)
    cudaFuncSetAttribute(k_fused, cudaFuncAttributeMaxDynamicSharedMemorySize, FUSED_SMEM);
    k_fused<<<(GM + BM - 1) / BM, 512, FUSED_SMEM>>>(out);
}